// round 2
// baseline (speedup 1.0000x reference)
#include <cuda_runtime.h>
#include <cuda_bf16.h>

// Polarisation (Thole dipole-dipole tensor), per-edge map.
// Inputs (metadata order): species[i32 N], edge_src[i32 E], edge_dst[i32 E],
//                          distances[f32 E], vec[f32 E*3], polarisability[f32 N]
// Output: t_matrix [E,3,3] f32.
//
// Math (after unit-conversion cancellation, all in angstrom):
//   au3 = 0.39 * d^3 * rsqrt(ps*pd)
//   e   = exp(-au3); l3 = 1-e; l5 = 1-(1+au3)*e
//   c3  = l3 * BOHR^3 / d^3 ; c5 = 3*l5 * BOHR^3 / d^5
//   T   = c5 * (v ⊗ v) - c3 * I

#define BOHR_F 0.52917721067f
#define A_MUT  0.39f
#define TPB    256

__global__ void __launch_bounds__(TPB)
thole_tensor_kernel(const int* __restrict__ edge_src,
                    const int* __restrict__ edge_dst,
                    const float* __restrict__ dist,
                    const float* __restrict__ vec,
                    const float* __restrict__ pol,
                    float* __restrict__ out,
                    int E)
{
    __shared__ float s[TPB * 9];   // 9 KB staging for coalesced output

    const int tid = threadIdx.x;
    const int e   = blockIdx.x * TPB + tid;

    float t[9];
    if (e < E) {
        // Issue the dependent gather chain first so the index loads and the
        // pol loads overlap with the streaming dist/vec loads.
        const int   is = edge_src[e];
        const int   id = edge_dst[e];
        const float ps = __ldg(&pol[is]);
        const float pd = __ldg(&pol[id]);

        const float d  = dist[e];
        const float vx = vec[3 * e + 0];
        const float vy = vec[3 * e + 1];
        const float vz = vec[3 * e + 2];

        const float inv_d  = 1.0f / d;
        const float inv_d2 = inv_d * inv_d;
        const float inv_d3 = inv_d2 * inv_d;
        const float inv_d5 = inv_d3 * inv_d2;

        const float au3 = A_MUT * (d * d * d) * rsqrtf(ps * pd);
        const float ex  = __expf(-au3);
        const float l3  = 1.0f - ex;
        const float l5  = 1.0f - (1.0f + au3) * ex;

        const float k  = BOHR_F * BOHR_F * BOHR_F;
        const float c3 = l3 * k * inv_d3;
        const float c5 = 3.0f * l5 * k * inv_d5;

        t[0] = c5 * vx * vx - c3;
        t[1] = c5 * vx * vy;
        t[2] = c5 * vx * vz;
        t[3] = t[1];
        t[4] = c5 * vy * vy - c3;
        t[5] = c5 * vy * vz;
        t[6] = t[2];
        t[7] = t[5];
        t[8] = c5 * vz * vz - c3;
    } else {
        #pragma unroll
        for (int i = 0; i < 9; i++) t[i] = 0.0f;
    }

    // Stage: stride-9 word writes -> bank-conflict-free (gcd(9,32)=1)
    #pragma unroll
    for (int i = 0; i < 9; i++) s[tid * 9 + i] = t[i];
    __syncthreads();

    const long long blk_base = (long long)blockIdx.x * (TPB * 9);
    const long long total    = (long long)E * 9;

    if (blk_base + TPB * 9 <= total) {
        // Full block: 2304 floats = 576 float4, perfectly coalesced.
        // blk_base*4 bytes = blockIdx*9216 B, 16B-aligned.
        float4* __restrict__ out4 = reinterpret_cast<float4*>(out + blk_base);
        const float4* __restrict__ s4 = reinterpret_cast<const float4*>(s);
        #pragma unroll
        for (int i = 0; i < 2; i++)
            out4[i * TPB + tid] = s4[i * TPB + tid];
        if (tid < 576 - 2 * TPB)
            out4[2 * TPB + tid] = s4[2 * TPB + tid];
    } else {
        // Tail block: scalar coalesced with bounds check.
        #pragma unroll
        for (int i = 0; i < 9; i++) {
            long long idx = blk_base + i * TPB + tid;
            if (idx < total) out[idx] = s[i * TPB + tid];
        }
    }
}

extern "C" void kernel_launch(void* const* d_in, const int* in_sizes, int n_in,
                              void* d_out, int out_size)
{
    // metadata order: species, edge_src, edge_dst, distances, vec, polarisability
    const int*   edge_src = (const int*)d_in[1];
    const int*   edge_dst = (const int*)d_in[2];
    const float* dist     = (const float*)d_in[3];
    const float* vec      = (const float*)d_in[4];
    const float* pol      = (const float*)d_in[5];
    float*       out      = (float*)d_out;

    const int E = in_sizes[1];
    const int grid = (E + TPB - 1) / TPB;
    thole_tensor_kernel<<<grid, TPB>>>(edge_src, edge_dst, dist, vec, pol, out, E);
}

// round 3
// speedup vs baseline: 1.0096x; 1.0096x over previous
#include <cuda_runtime.h>
#include <cuda_bf16.h>

// Polarisation (Thole dipole-dipole tensor), per-edge map.
// Inputs (metadata order): species[i32 N], edge_src[i32 E], edge_dst[i32 E],
//                          distances[f32 E], vec[f32 E*3], polarisability[f32 N]
// Output: t_matrix [E,3,3] f32.
//
// Math (after unit-conversion cancellation, all in angstrom):
//   au3 = 0.39 * d^3 * rsqrt(ps*pd)
//   e   = exp(-au3); l3 = 1-e; l5 = 1-(1+au3)*e
//   c3  = l3 * BOHR^3 / d^3 ; c5 = 3*l5 * BOHR^3 / d^5
//   T   = c5 * (v ⊗ v) - c3 * I

#define BOHR_F 0.52917721067f
#define A_MUT  0.39f
#define TPB    256

__global__ void __launch_bounds__(TPB)
thole_tensor_kernel(const int* __restrict__ edge_src,
                    const int* __restrict__ edge_dst,
                    const float* __restrict__ dist,
                    const float* __restrict__ vec,
                    const float* __restrict__ pol,
                    float* __restrict__ out,
                    int E)
{
    __shared__ float s[TPB * 9];   // 9 KB staging for coalesced output

    const int tid = threadIdx.x;
    const int e   = blockIdx.x * TPB + tid;

    float t[9];
    if (e < E) {
        // Issue the dependent gather chain first so the index loads and the
        // pol loads overlap with the streaming dist/vec loads.
        const int   is = edge_src[e];
        const int   id = edge_dst[e];
        const float ps = __ldg(&pol[is]);
        const float pd = __ldg(&pol[id]);

        const float d  = dist[e];
        const float vx = vec[3 * e + 0];
        const float vy = vec[3 * e + 1];
        const float vz = vec[3 * e + 2];

        const float inv_d  = 1.0f / d;
        const float inv_d2 = inv_d * inv_d;
        const float inv_d3 = inv_d2 * inv_d;
        const float inv_d5 = inv_d3 * inv_d2;

        const float au3 = A_MUT * (d * d * d) * rsqrtf(ps * pd);
        const float ex  = __expf(-au3);
        const float l3  = 1.0f - ex;
        const float l5  = 1.0f - (1.0f + au3) * ex;

        const float k  = BOHR_F * BOHR_F * BOHR_F;
        const float c3 = l3 * k * inv_d3;
        const float c5 = 3.0f * l5 * k * inv_d5;

        t[0] = c5 * vx * vx - c3;
        t[1] = c5 * vx * vy;
        t[2] = c5 * vx * vz;
        t[3] = t[1];
        t[4] = c5 * vy * vy - c3;
        t[5] = c5 * vy * vz;
        t[6] = t[2];
        t[7] = t[5];
        t[8] = c5 * vz * vz - c3;
    } else {
        #pragma unroll
        for (int i = 0; i < 9; i++) t[i] = 0.0f;
    }

    // Stage: stride-9 word writes -> bank-conflict-free (gcd(9,32)=1)
    #pragma unroll
    for (int i = 0; i < 9; i++) s[tid * 9 + i] = t[i];
    __syncthreads();

    const long long blk_base = (long long)blockIdx.x * (TPB * 9);
    const long long total    = (long long)E * 9;

    if (blk_base + TPB * 9 <= total) {
        // Full block: 2304 floats = 576 float4, perfectly coalesced.
        // blk_base*4 bytes = blockIdx*9216 B, 16B-aligned.
        float4* __restrict__ out4 = reinterpret_cast<float4*>(out + blk_base);
        const float4* __restrict__ s4 = reinterpret_cast<const float4*>(s);
        #pragma unroll
        for (int i = 0; i < 2; i++)
            out4[i * TPB + tid] = s4[i * TPB + tid];
        if (tid < 576 - 2 * TPB)
            out4[2 * TPB + tid] = s4[2 * TPB + tid];
    } else {
        // Tail block: scalar coalesced with bounds check.
        #pragma unroll
        for (int i = 0; i < 9; i++) {
            long long idx = blk_base + i * TPB + tid;
            if (idx < total) out[idx] = s[i * TPB + tid];
        }
    }
}

extern "C" void kernel_launch(void* const* d_in, const int* in_sizes, int n_in,
                              void* d_out, int out_size)
{
    // metadata order: species, edge_src, edge_dst, distances, vec, polarisability
    const int*   edge_src = (const int*)d_in[1];
    const int*   edge_dst = (const int*)d_in[2];
    const float* dist     = (const float*)d_in[3];
    const float* vec      = (const float*)d_in[4];
    const float* pol      = (const float*)d_in[5];
    float*       out      = (float*)d_out;

    const int E = in_sizes[1];
    const int grid = (E + TPB - 1) / TPB;
    thole_tensor_kernel<<<grid, TPB>>>(edge_src, edge_dst, dist, vec, pol, out, E);
}